// round 9
// baseline (speedup 1.0000x reference)
#include <cuda_runtime.h>

#define NN 100000
#define NE 1600000
#define NF 128
#define NG 512
#define SCAN_BS 1024
#define SCAN_NB ((NN + SCAN_BS - 1) / SCAN_BS)   // 98

// ---------------- scratch (no allocations allowed) ----------------
__device__ float g_dinv[NN];
__device__ int   g_cnt[NN];
__device__ int   g_start[NN];
__device__ int   g_fill[NN];
__device__ int   g_col[NE];
__device__ float g_B0[(size_t)NN * NF];   // node features (layer input)
__device__ float g_B1[(size_t)NN * NF];   // hs = (h@W)*dinv
__device__ float g_pool[NG];
__device__ int   g_gcnt[NG];
__device__ int   g_bsum[SCAN_NB + 8];

// ---------------- init ----------------
__global__ void k_init() {
    int i = blockIdx.x * blockDim.x + threadIdx.x;
    if (i < NN) { g_cnt[i] = 0; g_fill[i] = 0; }
    if (i < NG) { g_pool[i] = 0.0f; g_gcnt[i] = 0; }
}

// ---------------- degree histogram (in-degree by dst) ----------------
// edge_index is int32 (JAX default x64-disabled downcasts int64 -> int32).
__global__ void k_deg(const int* __restrict__ ei) {
    int e = blockIdx.x * blockDim.x + threadIdx.x;
    if (e >= NE) return;
    int dst = ei[NE + e];
    atomicAdd(&g_cnt[dst], 1);
}

// ---------------- per-graph node counts ----------------
__global__ void k_bcnt(const int* __restrict__ batch) {
    int i = blockIdx.x * blockDim.x + threadIdx.x;
    if (i >= NN) return;
    atomicAdd(&g_gcnt[batch[i]], 1);
}

// ---------------- 3-phase exclusive scan of g_cnt -> g_start ----------------
__global__ void k_scan1() {
    __shared__ int sh[SCAN_BS];
    int i = blockIdx.x * SCAN_BS + threadIdx.x;
    int v = (i < NN) ? g_cnt[i] : 0;
    sh[threadIdx.x] = v;
    __syncthreads();
    for (int off = 1; off < SCAN_BS; off <<= 1) {
        int t = (threadIdx.x >= off) ? sh[threadIdx.x - off] : 0;
        __syncthreads();
        sh[threadIdx.x] += t;
        __syncthreads();
    }
    int incl = sh[threadIdx.x];
    if (i < NN) g_start[i] = incl - v;
    if (threadIdx.x == SCAN_BS - 1) g_bsum[blockIdx.x] = incl;
}

__global__ void k_scan2() {
    if (threadIdx.x == 0 && blockIdx.x == 0) {
        int run = 0;
        for (int b = 0; b < SCAN_NB; b++) {
            int t = g_bsum[b];
            g_bsum[b] = run;
            run += t;
        }
    }
}

__global__ void k_scan3() {
    int i = blockIdx.x * blockDim.x + threadIdx.x;
    if (i >= NN) return;
    g_start[i] += g_bsum[i >> 10];
    g_dinv[i] = rsqrtf((float)g_cnt[i] + 1.0f);   // +1 for self-loop
}

// ---------------- CSR fill ----------------
__global__ void k_fill(const int* __restrict__ ei) {
    int e = blockIdx.x * blockDim.x + threadIdx.x;
    if (e >= NE) return;
    int src = ei[e];
    int dst = ei[NE + e];
    int pos = g_start[dst] + atomicAdd(&g_fill[dst], 1);
    g_col[pos] = src;
}

// ---------------- GEMM: g_B1[r,:] = (X[r,:] @ W) * dinv[r] ----------------
// USE_B0: read rows from g_B0 (layer 2) instead of the external X (layer 1).
// Block: 64 rows x 128 cols, 256 threads, each thread 4x8 tile.
template <bool USE_B0>
__global__ __launch_bounds__(256) void k_gemm_dinv(
    const float* __restrict__ Xext, const float* __restrict__ W)
{
    const float* __restrict__ X = USE_B0 ? (const float*)g_B0 : Xext;
    float* __restrict__ Y = g_B1;

    __shared__ float sX[64][33];
    __shared__ float sW[32][128];
    int t = threadIdx.x;
    int row0 = blockIdx.x * 64;
    int tx = t & 15, ty = t >> 4;
    int r0 = ty * 4, c0 = tx * 8;

    float acc[4][8];
#pragma unroll
    for (int i = 0; i < 4; i++)
#pragma unroll
        for (int j = 0; j < 8; j++) acc[i][j] = 0.0f;

    for (int kt = 0; kt < NF; kt += 32) {
#pragma unroll
        for (int j = 0; j < 8; j++) {               // 64x32 X tile
            int idx = t + j * 256;
            int r = idx >> 5, k = idx & 31;
            int gr = row0 + r;
            sX[r][k] = (gr < NN) ? X[(size_t)gr * NF + kt + k] : 0.0f;
        }
#pragma unroll
        for (int j = 0; j < 16; j++) {              // 32x128 W tile
            int idx = t + j * 256;
            int k = idx >> 7, c = idx & 127;
            sW[k][c] = W[(size_t)(kt + k) * NF + c];
        }
        __syncthreads();
#pragma unroll
        for (int k = 0; k < 32; k++) {
            float xv[4];
#pragma unroll
            for (int i = 0; i < 4; i++) xv[i] = sX[r0 + i][k];
            float4 w0 = *(const float4*)&sW[k][c0];
            float4 w1 = *(const float4*)&sW[k][c0 + 4];
#pragma unroll
            for (int i = 0; i < 4; i++) {
                acc[i][0] += xv[i] * w0.x; acc[i][1] += xv[i] * w0.y;
                acc[i][2] += xv[i] * w0.z; acc[i][3] += xv[i] * w0.w;
                acc[i][4] += xv[i] * w1.x; acc[i][5] += xv[i] * w1.y;
                acc[i][6] += xv[i] * w1.z; acc[i][7] += xv[i] * w1.w;
            }
        }
        __syncthreads();
    }
#pragma unroll
    for (int i = 0; i < 4; i++) {
        int gr = row0 + r0 + i;
        if (gr < NN) {
            float dv = g_dinv[gr];
            float4 o0 = make_float4(acc[i][0] * dv, acc[i][1] * dv,
                                    acc[i][2] * dv, acc[i][3] * dv);
            float4 o1 = make_float4(acc[i][4] * dv, acc[i][5] * dv,
                                    acc[i][6] * dv, acc[i][7] * dv);
            *(float4*)&Y[(size_t)gr * NF + c0] = o0;
            *(float4*)&Y[(size_t)gr * NF + c0 + 4] = o1;
        }
    }
}

// ---- gather + relu: g_B0[n,:] = relu(dinv[n]*(g_B1[n]+sum_in g_B1[src]) + b) ----
__global__ __launch_bounds__(256) void k_gather_relu(const float* __restrict__ bias)
{
    int warp = (blockIdx.x * blockDim.x + threadIdx.x) >> 5;
    if (warp >= NN) return;
    int lane = threadIdx.x & 31;
    const float4* hs4 = (const float4*)g_B1;

    float4 a = hs4[(size_t)warp * 32 + lane];   // self-loop term
    int s = g_start[warp], c = g_cnt[warp];
    for (int j = 0; j < c; j++) {
        int src = g_col[s + j];
        float4 v = hs4[(size_t)src * 32 + lane];
        a.x += v.x; a.y += v.y; a.z += v.z; a.w += v.w;
    }
    float dv = g_dinv[warp];
    float4 b4 = ((const float4*)bias)[lane];
    float4 o;
    o.x = fmaxf(a.x * dv + b4.x, 0.0f);
    o.y = fmaxf(a.y * dv + b4.y, 0.0f);
    o.z = fmaxf(a.z * dv + b4.z, 0.0f);
    o.w = fmaxf(a.w * dv + b4.w, 0.0f);
    ((float4*)g_B0)[(size_t)warp * 32 + lane] = o;
}

// ---- layer-2 gather fused with relu + Wout dot + pooling sum (reads g_B1) ----
__global__ __launch_bounds__(256) void k_gather_pool(
    const float* __restrict__ bias, const float* __restrict__ Wout,
    const int* __restrict__ batch)
{
    int warp = (blockIdx.x * blockDim.x + threadIdx.x) >> 5;
    if (warp >= NN) return;
    int lane = threadIdx.x & 31;
    const float4* hs4 = (const float4*)g_B1;

    float4 a = hs4[(size_t)warp * 32 + lane];
    int s = g_start[warp], c = g_cnt[warp];
    for (int j = 0; j < c; j++) {
        int src = g_col[s + j];
        float4 v = hs4[(size_t)src * 32 + lane];
        a.x += v.x; a.y += v.y; a.z += v.z; a.w += v.w;
    }
    float dv = g_dinv[warp];
    float4 b4 = ((const float4*)bias)[lane];
    float4 w4 = ((const float4*)Wout)[lane];
    float h0 = fmaxf(a.x * dv + b4.x, 0.0f);
    float h1 = fmaxf(a.y * dv + b4.y, 0.0f);
    float h2 = fmaxf(a.z * dv + b4.z, 0.0f);
    float h3 = fmaxf(a.w * dv + b4.w, 0.0f);
    float sdot = h0 * w4.x + h1 * w4.y + h2 * w4.z + h3 * w4.w;
#pragma unroll
    for (int off = 16; off > 0; off >>= 1)
        sdot += __shfl_down_sync(0xffffffffu, sdot, off);
    if (lane == 0)
        atomicAdd(&g_pool[batch[warp]], sdot);
}

// ---------------- final: out[g] = pool[g]/max(cnt,1) + bout ----------------
__global__ void k_final(float* __restrict__ out, const float* __restrict__ bout) {
    int g = blockIdx.x * blockDim.x + threadIdx.x;
    if (g >= NG) return;
    float c = fmaxf((float)g_gcnt[g], 1.0f);
    out[g] = g_pool[g] / c + bout[0];
}

// ---------------- launch (pure kernel launches; graph-capturable) ----------------
extern "C" void kernel_launch(void* const* d_in, const int* in_sizes, int n_in,
                              void* d_out, int out_size)
{
    const float* x     = (const float*)d_in[0];
    const int*   ei    = (const int*)d_in[1];     // int32! (JAX x64 disabled)
    const int*   batch = (const int*)d_in[2];     // int32!
    const float* W1    = (const float*)d_in[3];
    const float* b1    = (const float*)d_in[4];
    const float* W2    = (const float*)d_in[5];
    const float* b2    = (const float*)d_in[6];
    const float* Wout  = (const float*)d_in[7];
    const float* bout  = (const float*)d_in[8];
    float*       out   = (float*)d_out;

    const int TB = 256;
    // graph preprocessing (rebuilt every call; deterministic)
    k_init <<<(NN + TB - 1) / TB, TB>>>();
    k_deg  <<<(NE + TB - 1) / TB, TB>>>(ei);
    k_bcnt <<<(NN + TB - 1) / TB, TB>>>(batch);
    k_scan1<<<SCAN_NB, SCAN_BS>>>();
    k_scan2<<<1, 32>>>();
    k_scan3<<<(NN + TB - 1) / TB, TB>>>();
    k_fill <<<(NE + TB - 1) / TB, TB>>>(ei);

    // layer 1: g_B1 = (x@W1)*dinv  ->  g_B0 = relu(dinv*(self + gather) + b1)
    k_gemm_dinv<false><<<(NN + 63) / 64, 256>>>(x, W1);
    k_gather_relu<<<(NN * 32 + TB - 1) / TB, TB>>>(b1);

    // layer 2: g_B1 = (g_B0@W2)*dinv -> fused gather+relu+Wout-dot+pool
    k_gemm_dinv<true><<<(NN + 63) / 64, 256>>>(nullptr, W2);
    k_gather_pool<<<(NN * 32 + TB - 1) / TB, TB>>>(b2, Wout, batch);

    k_final<<<(NG + TB - 1) / TB, TB>>>(out, bout);
}

// round 11
// speedup vs baseline: 1.5454x; 1.5454x over previous
#include <cuda_runtime.h>
#include <cstdint>

#define NN 100000
#define NE 1600000
#define NF 128
#define NG 512
#define SCAN_BS 1024
#define SCAN_NB ((NN + SCAN_BS - 1) / SCAN_BS)   // 98
#define NT ((NN + 127) / 128)                    // 782 M-tiles

// ---------------- scratch (no allocations allowed) ----------------
__device__ float g_dinv[NN];
__device__ int   g_cnt[NN];
__device__ int   g_start[NN];
__device__ int   g_fill[NN];
__device__ int   g_col[NE];
__device__ float g_B0[(size_t)NN * NF];   // layer-1 activations (gather output)
__device__ float g_B1[(size_t)NN * NF];   // hs = (h@W)*dinv (GEMM output)
__device__ float g_pool[NG];
__device__ int   g_gcnt[NG];
__device__ int   g_bsum[SCAN_NB + 8];

// ---------------- init ----------------
__global__ void k_init() {
    int i = blockIdx.x * blockDim.x + threadIdx.x;
    if (i < NN) { g_cnt[i] = 0; g_fill[i] = 0; }
    if (i < NG) { g_pool[i] = 0.0f; g_gcnt[i] = 0; }
}

// edge_index / batch are int32 (JAX x64 disabled).
__global__ void k_deg(const int* __restrict__ ei) {
    int e = blockIdx.x * blockDim.x + threadIdx.x;
    if (e >= NE) return;
    atomicAdd(&g_cnt[ei[NE + e]], 1);
}

__global__ void k_bcnt(const int* __restrict__ batch) {
    int i = blockIdx.x * blockDim.x + threadIdx.x;
    if (i >= NN) return;
    atomicAdd(&g_gcnt[batch[i]], 1);
}

__global__ void k_scan1() {
    __shared__ int sh[SCAN_BS];
    int i = blockIdx.x * SCAN_BS + threadIdx.x;
    int v = (i < NN) ? g_cnt[i] : 0;
    sh[threadIdx.x] = v;
    __syncthreads();
    for (int off = 1; off < SCAN_BS; off <<= 1) {
        int t = (threadIdx.x >= off) ? sh[threadIdx.x - off] : 0;
        __syncthreads();
        sh[threadIdx.x] += t;
        __syncthreads();
    }
    int incl = sh[threadIdx.x];
    if (i < NN) g_start[i] = incl - v;
    if (threadIdx.x == SCAN_BS - 1) g_bsum[blockIdx.x] = incl;
}

__global__ void k_scan2() {
    if (threadIdx.x == 0 && blockIdx.x == 0) {
        int run = 0;
        for (int b = 0; b < SCAN_NB; b++) { int t = g_bsum[b]; g_bsum[b] = run; run += t; }
    }
}

__global__ void k_scan3() {
    int i = blockIdx.x * blockDim.x + threadIdx.x;
    if (i >= NN) return;
    g_start[i] += g_bsum[i >> 10];
    g_dinv[i] = rsqrtf((float)g_cnt[i] + 1.0f);
}

__global__ void k_fill(const int* __restrict__ ei) {
    int e = blockIdx.x * blockDim.x + threadIdx.x;
    if (e >= NE) return;
    int src = ei[e];
    int dst = ei[NE + e];
    int pos = g_start[dst] + atomicAdd(&g_fill[dst], 1);
    g_col[pos] = src;
}

// ================== tf32 tensor-core GEMM ==================
// g_B1[r,:] = (X[r,:] @ W) * dinv[r]
// Baseline-PTX mma.sync m16n8k8 tf32 (works on plain sm_103 target).
// W split into Whi + Wlo (2 MMA passes, fp32 accum) to kill the correlated
// tf32 rounding error of the shared weight matrix; A pre-rounded with cvt.rna
// (unbiased, per-node error that pooling averages out).

__device__ __forceinline__ float tf32r(float x) {
    float r;
    asm("cvt.rna.tf32.f32 %0, %1;" : "=f"(r) : "f"(x));
    return r;
}

__device__ __forceinline__ void mma_tf32(float* c, const uint32_t* a, const uint32_t* b) {
    asm volatile(
        "mma.sync.aligned.m16n8k8.row.col.f32.tf32.tf32.f32 "
        "{%0,%1,%2,%3}, {%4,%5,%6,%7}, {%8,%9}, {%0,%1,%2,%3};"
        : "+f"(c[0]), "+f"(c[1]), "+f"(c[2]), "+f"(c[3])
        : "r"(a[0]), "r"(a[1]), "r"(a[2]), "r"(a[3]), "r"(b[0]), "r"(b[1]));
}

// Block: 128x128 output, 256 threads = 8 warps (2 m x 4 n), warp tile 64x32.
// K chunked by 16 (2 k8-steps per chunk), W hi/lo per chunk in smem.
template <bool USE_B0>
__global__ __launch_bounds__(256, 2) void k_mma_gemm(
    const float* __restrict__ Xext, const float* __restrict__ W)
{
    const float* __restrict__ X = USE_B0 ? (const float*)g_B0 : Xext;

    __shared__ float sA[128][20];     // 128 rows x 16 k, pad 20 -> conflict-free frag loads
    __shared__ float sWhi[16][136];   // 16 k x 128 n, pad 136 -> bank 8k+n, conflict-free
    __shared__ float sWlo[16][136];

    int tid = threadIdx.x;
    int lane = tid & 31, w = tid >> 5;
    int warp_m = w >> 2, warp_n = w & 3;      // 2 x 4 warps
    int row0 = blockIdx.x * 128;

    float acc[4][4][4];
#pragma unroll
    for (int a = 0; a < 4; a++)
#pragma unroll
        for (int b = 0; b < 4; b++)
#pragma unroll
            for (int c = 0; c < 4; c++) acc[a][b][c] = 0.0f;

    for (int kc = 0; kc < 8; kc++) {
        int k0 = kc * 16;
        // A chunk: 128 x 16 floats (512 float4)
#pragma unroll
        for (int it = 0; it < 2; it++) {
            int i = tid + it * 256;
            int r = i >> 2, c4 = (i & 3) * 4;
            int gr = row0 + r;
            float4 v = (gr < NN) ? *(const float4*)&X[(size_t)gr * NF + k0 + c4]
                                 : make_float4(0.f, 0.f, 0.f, 0.f);
            sA[r][c4 + 0] = tf32r(v.x);
            sA[r][c4 + 1] = tf32r(v.y);
            sA[r][c4 + 2] = tf32r(v.z);
            sA[r][c4 + 3] = tf32r(v.w);
        }
        // W chunk: 16 x 128 floats, hi/lo split
#pragma unroll
        for (int it = 0; it < 2; it++) {
            int i = tid + it * 256;
            int r = i >> 5, c4 = (i & 31) * 4;
            float4 v = *(const float4*)&W[(size_t)(k0 + r) * NF + c4];
            float hx = tf32r(v.x), hy = tf32r(v.y), hz = tf32r(v.z), hw = tf32r(v.w);
            sWhi[r][c4 + 0] = hx; sWhi[r][c4 + 1] = hy;
            sWhi[r][c4 + 2] = hz; sWhi[r][c4 + 3] = hw;
            sWlo[r][c4 + 0] = tf32r(v.x - hx); sWlo[r][c4 + 1] = tf32r(v.y - hy);
            sWlo[r][c4 + 2] = tf32r(v.z - hz); sWlo[r][c4 + 3] = tf32r(v.w - hw);
        }
        __syncthreads();

#pragma unroll
        for (int ks = 0; ks < 2; ks++) {
            int kb = ks * 8;
            // A fragments (4 m-tiles)
            uint32_t af[4][4];
#pragma unroll
            for (int mt = 0; mt < 4; mt++) {
                int ar = warp_m * 64 + mt * 16 + (lane >> 2);
                int ac = kb + (lane & 3);
                af[mt][0] = __float_as_uint(sA[ar][ac]);
                af[mt][1] = __float_as_uint(sA[ar + 8][ac]);
                af[mt][2] = __float_as_uint(sA[ar][ac + 4]);
                af[mt][3] = __float_as_uint(sA[ar + 8][ac + 4]);
            }
            // B fragments hi/lo (4 n-tiles)
            uint32_t bh[4][2], bl[4][2];
#pragma unroll
            for (int nt = 0; nt < 4; nt++) {
                int bn = warp_n * 32 + nt * 8 + (lane >> 2);
                int bk = kb + (lane & 3);
                bh[nt][0] = __float_as_uint(sWhi[bk][bn]);
                bh[nt][1] = __float_as_uint(sWhi[bk + 4][bn]);
                bl[nt][0] = __float_as_uint(sWlo[bk][bn]);
                bl[nt][1] = __float_as_uint(sWlo[bk + 4][bn]);
            }
#pragma unroll
            for (int mt = 0; mt < 4; mt++)
#pragma unroll
                for (int nt = 0; nt < 4; nt++) {
                    mma_tf32(acc[mt][nt], af[mt], bh[nt]);
                    mma_tf32(acc[mt][nt], af[mt], bl[nt]);
                }
        }
        __syncthreads();
    }

    // epilogue: *dinv, store fp32
#pragma unroll
    for (int mt = 0; mt < 4; mt++) {
        int r1 = row0 + warp_m * 64 + mt * 16 + (lane >> 2);
        int r2 = r1 + 8;
        float dv1 = (r1 < NN) ? g_dinv[r1] : 0.0f;
        float dv2 = (r2 < NN) ? g_dinv[r2] : 0.0f;
#pragma unroll
        for (int nt = 0; nt < 4; nt++) {
            int c = warp_n * 32 + nt * 8 + (lane & 3) * 2;
            if (r1 < NN) {
                float2 o = make_float2(acc[mt][nt][0] * dv1, acc[mt][nt][1] * dv1);
                *(float2*)&g_B1[(size_t)r1 * NF + c] = o;
            }
            if (r2 < NN) {
                float2 o = make_float2(acc[mt][nt][2] * dv2, acc[mt][nt][3] * dv2);
                *(float2*)&g_B1[(size_t)r2 * NF + c] = o;
            }
        }
    }
}

// ---- gather + relu: g_B0[n,:] = relu(dinv[n]*(g_B1[n]+sum_in g_B1[src]) + b) ----
__global__ __launch_bounds__(256) void k_gather_relu(const float* __restrict__ bias)
{
    int warp = (blockIdx.x * blockDim.x + threadIdx.x) >> 5;
    if (warp >= NN) return;
    int lane = threadIdx.x & 31;
    const float4* hs4 = (const float4*)g_B1;

    float4 a = hs4[(size_t)warp * 32 + lane];   // self-loop term
    int s = g_start[warp], c = g_cnt[warp];
    for (int j = 0; j < c; j++) {
        int src = g_col[s + j];
        float4 v = hs4[(size_t)src * 32 + lane];
        a.x += v.x; a.y += v.y; a.z += v.z; a.w += v.w;
    }
    float dv = g_dinv[warp];
    float4 b4 = ((const float4*)bias)[lane];
    float4 o;
    o.x = fmaxf(a.x * dv + b4.x, 0.0f);
    o.y = fmaxf(a.y * dv + b4.y, 0.0f);
    o.z = fmaxf(a.z * dv + b4.z, 0.0f);
    o.w = fmaxf(a.w * dv + b4.w, 0.0f);
    ((float4*)g_B0)[(size_t)warp * 32 + lane] = o;
}

// ---- layer-2 gather fused with relu + Wout dot + pooling sum (reads g_B1) ----
__global__ __launch_bounds__(256) void k_gather_pool(
    const float* __restrict__ bias, const float* __restrict__ Wout,
    const int* __restrict__ batch)
{
    int warp = (blockIdx.x * blockDim.x + threadIdx.x) >> 5;
    if (warp >= NN) return;
    int lane = threadIdx.x & 31;
    const float4* hs4 = (const float4*)g_B1;

    float4 a = hs4[(size_t)warp * 32 + lane];
    int s = g_start[warp], c = g_cnt[warp];
    for (int j = 0; j < c; j++) {
        int src = g_col[s + j];
        float4 v = hs4[(size_t)src * 32 + lane];
        a.x += v.x; a.y += v.y; a.z += v.z; a.w += v.w;
    }
    float dv = g_dinv[warp];
    float4 b4 = ((const float4*)bias)[lane];
    float4 w4 = ((const float4*)Wout)[lane];
    float h0 = fmaxf(a.x * dv + b4.x, 0.0f);
    float h1 = fmaxf(a.y * dv + b4.y, 0.0f);
    float h2 = fmaxf(a.z * dv + b4.z, 0.0f);
    float h3 = fmaxf(a.w * dv + b4.w, 0.0f);
    float sdot = h0 * w4.x + h1 * w4.y + h2 * w4.z + h3 * w4.w;
#pragma unroll
    for (int off = 16; off > 0; off >>= 1)
        sdot += __shfl_down_sync(0xffffffffu, sdot, off);
    if (lane == 0)
        atomicAdd(&g_pool[batch[warp]], sdot);
}

__global__ void k_final(float* __restrict__ out, const float* __restrict__ bout) {
    int g = blockIdx.x * blockDim.x + threadIdx.x;
    if (g >= NG) return;
    float c = fmaxf((float)g_gcnt[g], 1.0f);
    out[g] = g_pool[g] / c + bout[0];
}

// ---------------- launch (kernel launches only; graph-capturable) ----------------
extern "C" void kernel_launch(void* const* d_in, const int* in_sizes, int n_in,
                              void* d_out, int out_size)
{
    const float* x     = (const float*)d_in[0];
    const int*   ei    = (const int*)d_in[1];     // int32 (JAX x64 disabled)
    const int*   batch = (const int*)d_in[2];
    const float* W1    = (const float*)d_in[3];
    const float* b1    = (const float*)d_in[4];
    const float* W2    = (const float*)d_in[5];
    const float* b2    = (const float*)d_in[6];
    const float* Wout  = (const float*)d_in[7];
    const float* bout  = (const float*)d_in[8];
    float*       out   = (float*)d_out;

    const int TB = 256;
    // graph preprocessing (rebuilt every call; deterministic)
    k_init <<<(NN + TB - 1) / TB, TB>>>();
    k_deg  <<<(NE + TB - 1) / TB, TB>>>(ei);
    k_bcnt <<<(NN + TB - 1) / TB, TB>>>(batch);
    k_scan1<<<SCAN_NB, SCAN_BS>>>();
    k_scan2<<<1, 32>>>();
    k_scan3<<<(NN + TB - 1) / TB, TB>>>();
    k_fill <<<(NE + TB - 1) / TB, TB>>>(ei);

    // layer 1: g_B1 = (x@W1)*dinv  ->  g_B0 = relu(dinv*(self + gather) + b1)
    k_mma_gemm<false><<<NT, 256>>>(x, W1);
    k_gather_relu<<<(NN * 32 + TB - 1) / TB, TB>>>(b1);

    // layer 2: g_B1 = (g_B0@W2)*dinv -> fused gather+relu+Wout-dot+pool
    k_mma_gemm<true><<<NT, 256>>>(nullptr, W2);
    k_gather_pool<<<(NN * 32 + TB - 1) / TB, TB>>>(b2, Wout, batch);

    k_final<<<(NG + TB - 1) / TB, TB>>>(out, bout);
}

// round 12
// speedup vs baseline: 1.6034x; 1.0376x over previous
#include <cuda_runtime.h>
#include <cuda_fp16.h>
#include <cstdint>

#define NN 100000
#define NE 1600000
#define NF 128
#define NG 512
#define SCAN_BS 1024
#define SCAN_NB ((NN + SCAN_BS - 1) / SCAN_BS)   // 98
#define NT ((NN + 127) / 128)                    // 782 M-tiles

// ---------------- scratch (no allocations allowed) ----------------
__device__ float   g_dinv[NN];
__device__ int     g_cnt[NN];
__device__ int     g_start[NN];
__device__ int     g_fill[NN];
__device__ int     g_col[NE];
__device__ float   g_B0[(size_t)NN * NF];        // layer-1 activations (gather output, fp32)
__device__ __half2 g_H[(size_t)NN * (NF / 2)];   // hs = (h@W)*dinv, fp16 (gather input)
__device__ float   g_pool[NG];
__device__ int     g_gcnt[NG];
__device__ int     g_bsum[SCAN_NB + 8];

// ---------------- init ----------------
__global__ void k_init() {
    int i = blockIdx.x * blockDim.x + threadIdx.x;
    if (i < NN) { g_cnt[i] = 0; g_fill[i] = 0; }
    if (i < NG) { g_pool[i] = 0.0f; g_gcnt[i] = 0; }
}

// edge_index / batch are int32 (JAX x64 disabled).
// Fused: in-degree histogram + per-graph node counts.
__global__ void k_deg(const int* __restrict__ ei, const int* __restrict__ batch) {
    int e = blockIdx.x * blockDim.x + threadIdx.x;
    if (e < NE) atomicAdd(&g_cnt[ei[NE + e]], 1);
    if (e < NN) atomicAdd(&g_gcnt[batch[e]], 1);
}

__global__ void k_scan1() {
    __shared__ int sh[SCAN_BS];
    int i = blockIdx.x * SCAN_BS + threadIdx.x;
    int v = (i < NN) ? g_cnt[i] : 0;
    sh[threadIdx.x] = v;
    __syncthreads();
    for (int off = 1; off < SCAN_BS; off <<= 1) {
        int t = (threadIdx.x >= off) ? sh[threadIdx.x - off] : 0;
        __syncthreads();
        sh[threadIdx.x] += t;
        __syncthreads();
    }
    int incl = sh[threadIdx.x];
    if (i < NN) g_start[i] = incl - v;
    if (threadIdx.x == SCAN_BS - 1) g_bsum[blockIdx.x] = incl;
}

__global__ void k_scan2() {
    if (threadIdx.x == 0 && blockIdx.x == 0) {
        int run = 0;
        for (int b = 0; b < SCAN_NB; b++) { int t = g_bsum[b]; g_bsum[b] = run; run += t; }
    }
}

__global__ void k_scan3() {
    int i = blockIdx.x * blockDim.x + threadIdx.x;
    if (i >= NN) return;
    g_start[i] += g_bsum[i >> 10];
    g_dinv[i] = rsqrtf((float)g_cnt[i] + 1.0f);
}

__global__ void k_fill(const int* __restrict__ ei) {
    int e = blockIdx.x * blockDim.x + threadIdx.x;
    if (e >= NE) return;
    int src = ei[e];
    int dst = ei[NE + e];
    int pos = g_start[dst] + atomicAdd(&g_fill[dst], 1);
    g_col[pos] = src;
}

// ================== tf32 tensor-core GEMM ==================
// g_H[r,:] = fp16( (X[r,:] @ W) * dinv[r] )
// Baseline-PTX mma.sync m16n8k8 tf32; W split hi+lo (2 MMA passes, fp32 accum).

__device__ __forceinline__ float tf32r(float x) {
    float r;
    asm("cvt.rna.tf32.f32 %0, %1;" : "=f"(r) : "f"(x));
    return r;
}

__device__ __forceinline__ void mma_tf32(float* c, const uint32_t* a, const uint32_t* b) {
    asm volatile(
        "mma.sync.aligned.m16n8k8.row.col.f32.tf32.tf32.f32 "
        "{%0,%1,%2,%3}, {%4,%5,%6,%7}, {%8,%9}, {%0,%1,%2,%3};"
        : "+f"(c[0]), "+f"(c[1]), "+f"(c[2]), "+f"(c[3])
        : "r"(a[0]), "r"(a[1]), "r"(a[2]), "r"(a[3]), "r"(b[0]), "r"(b[1]));
}

// Block: 128x128 output, 256 threads = 8 warps (2 m x 4 n), warp tile 64x32.
template <bool USE_B0>
__global__ __launch_bounds__(256, 2) void k_mma_gemm(
    const float* __restrict__ Xext, const float* __restrict__ W)
{
    const float* __restrict__ X = USE_B0 ? (const float*)g_B0 : Xext;

    __shared__ float sA[128][20];
    __shared__ float sWhi[16][136];
    __shared__ float sWlo[16][136];

    int tid = threadIdx.x;
    int lane = tid & 31, w = tid >> 5;
    int warp_m = w >> 2, warp_n = w & 3;
    int row0 = blockIdx.x * 128;

    float acc[4][4][4];
#pragma unroll
    for (int a = 0; a < 4; a++)
#pragma unroll
        for (int b = 0; b < 4; b++)
#pragma unroll
            for (int c = 0; c < 4; c++) acc[a][b][c] = 0.0f;

    for (int kc = 0; kc < 8; kc++) {
        int k0 = kc * 16;
#pragma unroll
        for (int it = 0; it < 2; it++) {
            int i = tid + it * 256;
            int r = i >> 2, c4 = (i & 3) * 4;
            int gr = row0 + r;
            float4 v = (gr < NN) ? *(const float4*)&X[(size_t)gr * NF + k0 + c4]
                                 : make_float4(0.f, 0.f, 0.f, 0.f);
            sA[r][c4 + 0] = tf32r(v.x);
            sA[r][c4 + 1] = tf32r(v.y);
            sA[r][c4 + 2] = tf32r(v.z);
            sA[r][c4 + 3] = tf32r(v.w);
        }
#pragma unroll
        for (int it = 0; it < 2; it++) {
            int i = tid + it * 256;
            int r = i >> 5, c4 = (i & 31) * 4;
            float4 v = *(const float4*)&W[(size_t)(k0 + r) * NF + c4];
            float hx = tf32r(v.x), hy = tf32r(v.y), hz = tf32r(v.z), hw = tf32r(v.w);
            sWhi[r][c4 + 0] = hx; sWhi[r][c4 + 1] = hy;
            sWhi[r][c4 + 2] = hz; sWhi[r][c4 + 3] = hw;
            sWlo[r][c4 + 0] = tf32r(v.x - hx); sWlo[r][c4 + 1] = tf32r(v.y - hy);
            sWlo[r][c4 + 2] = tf32r(v.z - hz); sWlo[r][c4 + 3] = tf32r(v.w - hw);
        }
        __syncthreads();

#pragma unroll
        for (int ks = 0; ks < 2; ks++) {
            int kb = ks * 8;
            uint32_t af[4][4];
#pragma unroll
            for (int mt = 0; mt < 4; mt++) {
                int ar = warp_m * 64 + mt * 16 + (lane >> 2);
                int ac = kb + (lane & 3);
                af[mt][0] = __float_as_uint(sA[ar][ac]);
                af[mt][1] = __float_as_uint(sA[ar + 8][ac]);
                af[mt][2] = __float_as_uint(sA[ar][ac + 4]);
                af[mt][3] = __float_as_uint(sA[ar + 8][ac + 4]);
            }
            uint32_t bh[4][2], bl[4][2];
#pragma unroll
            for (int nt = 0; nt < 4; nt++) {
                int bn = warp_n * 32 + nt * 8 + (lane >> 2);
                int bk = kb + (lane & 3);
                bh[nt][0] = __float_as_uint(sWhi[bk][bn]);
                bh[nt][1] = __float_as_uint(sWhi[bk + 4][bn]);
                bl[nt][0] = __float_as_uint(sWlo[bk][bn]);
                bl[nt][1] = __float_as_uint(sWlo[bk + 4][bn]);
            }
#pragma unroll
            for (int mt = 0; mt < 4; mt++)
#pragma unroll
                for (int nt = 0; nt < 4; nt++) {
                    mma_tf32(acc[mt][nt], af[mt], bh[nt]);
                    mma_tf32(acc[mt][nt], af[mt], bl[nt]);
                }
        }
        __syncthreads();
    }

    // epilogue: *dinv, convert to fp16, store half2
#pragma unroll
    for (int mt = 0; mt < 4; mt++) {
        int r1 = row0 + warp_m * 64 + mt * 16 + (lane >> 2);
        int r2 = r1 + 8;
        float dv1 = (r1 < NN) ? g_dinv[r1] : 0.0f;
        float dv2 = (r2 < NN) ? g_dinv[r2] : 0.0f;
#pragma unroll
        for (int nt = 0; nt < 4; nt++) {
            int h2i = warp_n * 16 + nt * 4 + (lane & 3);   // half2 column index
            if (r1 < NN)
                g_H[(size_t)r1 * 64 + h2i] = __float22half2_rn(
                    make_float2(acc[mt][nt][0] * dv1, acc[mt][nt][1] * dv1));
            if (r2 < NN)
                g_H[(size_t)r2 * 64 + h2i] = __float22half2_rn(
                    make_float2(acc[mt][nt][2] * dv2, acc[mt][nt][3] * dv2));
        }
    }
}

// ---- gather + relu: g_B0[n,:] = relu(dinv[n]*(hs[n]+sum_in hs[src]) + b) ----
// hs rows are fp16 (256 B); per-lane uint2 load = 2 half2 = cols [4*lane, 4*lane+4).
__global__ __launch_bounds__(256) void k_gather_relu(const float* __restrict__ bias)
{
    int warp = (blockIdx.x * blockDim.x + threadIdx.x) >> 5;
    if (warp >= NN) return;
    int lane = threadIdx.x & 31;

    const __half2* hs = g_H;
    size_t lidx = (size_t)warp * 64 + lane * 2;
    __half2 p0 = hs[lidx], p1 = hs[lidx + 1];
    float2 f0 = __half22float2(p0), f1 = __half22float2(p1);
    float ax = f0.x, ay = f0.y, az = f1.x, aw = f1.y;   // self-loop term

    int s = g_start[warp], c = g_cnt[warp];
#pragma unroll 4
    for (int j = 0; j < c; j++) {
        int src = g_col[s + j];
        size_t si = (size_t)src * 64 + lane * 2;
        __half2 q0 = hs[si], q1 = hs[si + 1];
        float2 g0 = __half22float2(q0), g1 = __half22float2(q1);
        ax += g0.x; ay += g0.y; az += g1.x; aw += g1.y;
    }
    float dv = g_dinv[warp];
    float4 b4 = ((const float4*)bias)[lane];
    float4 o;
    o.x = fmaxf(ax * dv + b4.x, 0.0f);
    o.y = fmaxf(ay * dv + b4.y, 0.0f);
    o.z = fmaxf(az * dv + b4.z, 0.0f);
    o.w = fmaxf(aw * dv + b4.w, 0.0f);
    ((float4*)g_B0)[(size_t)warp * 32 + lane] = o;
}

// ---- layer-2 gather fused with relu + Wout dot + pooling sum (reads g_H) ----
__global__ __launch_bounds__(256) void k_gather_pool(
    const float* __restrict__ bias, const float* __restrict__ Wout,
    const int* __restrict__ batch)
{
    int warp = (blockIdx.x * blockDim.x + threadIdx.x) >> 5;
    if (warp >= NN) return;
    int lane = threadIdx.x & 31;

    const __half2* hs = g_H;
    size_t lidx = (size_t)warp * 64 + lane * 2;
    __half2 p0 = hs[lidx], p1 = hs[lidx + 1];
    float2 f0 = __half22float2(p0), f1 = __half22float2(p1);
    float ax = f0.x, ay = f0.y, az = f1.x, aw = f1.y;

    int s = g_start[warp], c = g_cnt[warp];
#pragma unroll 4
    for (int j = 0; j < c; j++) {
        int src = g_col[s + j];
        size_t si = (size_t)src * 64 + lane * 2;
        __half2 q0 = hs[si], q1 = hs[si + 1];
        float2 g0 = __half22float2(q0), g1 = __half22float2(q1);
        ax += g0.x; ay += g0.y; az += g1.x; aw += g1.y;
    }
    float dv = g_dinv[warp];
    float4 b4 = ((const float4*)bias)[lane];
    float4 w4 = ((const float4*)Wout)[lane];
    float h0 = fmaxf(ax * dv + b4.x, 0.0f);
    float h1 = fmaxf(ay * dv + b4.y, 0.0f);
    float h2 = fmaxf(az * dv + b4.z, 0.0f);
    float h3 = fmaxf(aw * dv + b4.w, 0.0f);
    float sdot = h0 * w4.x + h1 * w4.y + h2 * w4.z + h3 * w4.w;
#pragma unroll
    for (int off = 16; off > 0; off >>= 1)
        sdot += __shfl_down_sync(0xffffffffu, sdot, off);
    if (lane == 0)
        atomicAdd(&g_pool[batch[warp]], sdot);
}

__global__ void k_final(float* __restrict__ out, const float* __restrict__ bout) {
    int g = blockIdx.x * blockDim.x + threadIdx.x;
    if (g >= NG) return;
    float c = fmaxf((float)g_gcnt[g], 1.0f);
    out[g] = g_pool[g] / c + bout[0];
}

// ---------------- launch (kernel launches only; graph-capturable) ----------------
extern "C" void kernel_launch(void* const* d_in, const int* in_sizes, int n_in,
                              void* d_out, int out_size)
{
    const float* x     = (const float*)d_in[0];
    const int*   ei    = (const int*)d_in[1];     // int32 (JAX x64 disabled)
    const int*   batch = (const int*)d_in[2];
    const float* W1    = (const float*)d_in[3];
    const float* b1    = (const float*)d_in[4];
    const float* W2    = (const float*)d_in[5];
    const float* b2    = (const float*)d_in[6];
    const float* Wout  = (const float*)d_in[7];
    const float* bout  = (const float*)d_in[8];
    float*       out   = (float*)d_out;

    const int TB = 256;
    // graph preprocessing (rebuilt every call; deterministic)
    k_init <<<(NN + TB - 1) / TB, TB>>>();
    k_deg  <<<(NE + TB - 1) / TB, TB>>>(ei, batch);
    k_scan1<<<SCAN_NB, SCAN_BS>>>();
    k_scan2<<<1, 32>>>();
    k_scan3<<<(NN + TB - 1) / TB, TB>>>();
    k_fill <<<(NE + TB - 1) / TB, TB>>>(ei);

    // layer 1: g_H = fp16((x@W1)*dinv)  ->  g_B0 = relu(dinv*(self + gather) + b1)
    k_mma_gemm<false><<<NT, 256>>>(x, W1);
    k_gather_relu<<<(NN * 32 + TB - 1) / TB, TB>>>(b1);

    // layer 2: g_H = fp16((g_B0@W2)*dinv) -> fused gather+relu+Wout-dot+pool
    k_mma_gemm<true><<<NT, 256>>>(nullptr, W2);
    k_gather_pool<<<(NN * 32 + TB - 1) / TB, TB>>>(b2, Wout, batch);

    k_final<<<(NG + TB - 1) / TB, TB>>>(out, bout);
}

// round 14
// speedup vs baseline: 1.7835x; 1.1123x over previous
#include <cuda_runtime.h>
#include <cuda_fp16.h>
#include <cstdint>

#define NN 100000
#define NE 1600000
#define NF 128
#define NG 512
#define SCAN_BS 1024
#define SCAN_NB ((NN + SCAN_BS - 1) / SCAN_BS)   // 98
#define NT ((NN + 127) / 128)                    // 782 M-tiles

// ---------------- scratch (no allocations allowed) ----------------
__device__ float   g_dinv[NN];
__device__ int     g_cnt[NN];
__device__ int     g_start[NN];
__device__ int     g_fill[NN];
__device__ int     g_col[NE];
__device__ float   g_B0[(size_t)NN * NF];        // layer-1 activations (gather output, fp32)
__device__ __half2 g_H[(size_t)NN * (NF / 2)];   // hs = (h@W)*dinv, fp16 (gather input)
__device__ float   g_pool[NG];
__device__ int     g_gcnt[NG];
__device__ int     g_bsum[SCAN_NB + 32];

// ---------------- init ----------------
__global__ void k_init() {
    int i = blockIdx.x * blockDim.x + threadIdx.x;
    if (i < NN) { g_cnt[i] = 0; g_fill[i] = 0; }
    if (i < NG) { g_pool[i] = 0.0f; g_gcnt[i] = 0; }
}

// edge_index / batch are int32 (JAX x64 disabled).
// Fused: in-degree histogram + per-graph node counts.
__global__ void k_deg(const int* __restrict__ ei, const int* __restrict__ batch) {
    int e = blockIdx.x * blockDim.x + threadIdx.x;
    if (e < NE) atomicAdd(&g_cnt[ei[NE + e]], 1);
    if (e < NN) atomicAdd(&g_gcnt[batch[e]], 1);
}

__global__ void k_scan1() {
    __shared__ int sh[SCAN_BS];
    int i = blockIdx.x * SCAN_BS + threadIdx.x;
    int v = (i < NN) ? g_cnt[i] : 0;
    sh[threadIdx.x] = v;
    __syncthreads();
    for (int off = 1; off < SCAN_BS; off <<= 1) {
        int t = (threadIdx.x >= off) ? sh[threadIdx.x - off] : 0;
        __syncthreads();
        sh[threadIdx.x] += t;
        __syncthreads();
    }
    int incl = sh[threadIdx.x];
    if (i < NN) g_start[i] = incl - v;
    if (threadIdx.x == SCAN_BS - 1) g_bsum[blockIdx.x] = incl;
}

// parallel block-scan of the 98 block sums (was a serial 1-thread loop, 8.2us)
__global__ void k_scan2() {
    __shared__ int sh[128];
    int t = threadIdx.x;
    int v = (t < SCAN_NB) ? g_bsum[t] : 0;
    sh[t] = v;
    __syncthreads();
    for (int off = 1; off < 128; off <<= 1) {
        int u = (t >= off) ? sh[t - off] : 0;
        __syncthreads();
        sh[t] += u;
        __syncthreads();
    }
    if (t < SCAN_NB) g_bsum[t] = sh[t] - v;   // exclusive
}

__global__ void k_scan3() {
    int i = blockIdx.x * blockDim.x + threadIdx.x;
    if (i >= NN) return;
    g_start[i] += g_bsum[i >> 10];
    g_dinv[i] = rsqrtf((float)g_cnt[i] + 1.0f);
}

__global__ void k_fill(const int* __restrict__ ei) {
    int e = blockIdx.x * blockDim.x + threadIdx.x;
    if (e >= NE) return;
    int src = ei[e];
    int dst = ei[NE + e];
    int pos = g_start[dst] + atomicAdd(&g_fill[dst], 1);
    g_col[pos] = src;
}

// ================== tf32 tensor-core GEMM ==================
// g_H[r,:] = fp16( (X[r,:] @ W) * dinv[r] )
// Single-pass tf32 (A and W cvt.rna); fp32 accumulate.

__device__ __forceinline__ float tf32r(float x) {
    float r;
    asm("cvt.rna.tf32.f32 %0, %1;" : "=f"(r) : "f"(x));
    return r;
}

__device__ __forceinline__ void mma_tf32(float* c, const uint32_t* a, const uint32_t* b) {
    asm volatile(
        "mma.sync.aligned.m16n8k8.row.col.f32.tf32.tf32.f32 "
        "{%0,%1,%2,%3}, {%4,%5,%6,%7}, {%8,%9}, {%0,%1,%2,%3};"
        : "+f"(c[0]), "+f"(c[1]), "+f"(c[2]), "+f"(c[3])
        : "r"(a[0]), "r"(a[1]), "r"(a[2]), "r"(a[3]), "r"(b[0]), "r"(b[1]));
}

// Block: 128x128 output, 256 threads = 8 warps (2 m x 4 n), warp tile 64x32.
template <bool USE_B0>
__global__ __launch_bounds__(256, 2) void k_mma_gemm(
    const float* __restrict__ Xext, const float* __restrict__ W)
{
    const float* __restrict__ X = USE_B0 ? (const float*)g_B0 : Xext;

    __shared__ float sA[128][20];
    __shared__ float sW[16][136];

    int tid = threadIdx.x;
    int lane = tid & 31, w = tid >> 5;
    int warp_m = w >> 2, warp_n = w & 3;
    int row0 = blockIdx.x * 128;

    float acc[4][4][4];
#pragma unroll
    for (int a = 0; a < 4; a++)
#pragma unroll
        for (int b = 0; b < 4; b++)
#pragma unroll
            for (int c = 0; c < 4; c++) acc[a][b][c] = 0.0f;

    for (int kc = 0; kc < 8; kc++) {
        int k0 = kc * 16;
#pragma unroll
        for (int it = 0; it < 2; it++) {
            int i = tid + it * 256;
            int r = i >> 2, c4 = (i & 3) * 4;
            int gr = row0 + r;
            float4 v = (gr < NN) ? *(const float4*)&X[(size_t)gr * NF + k0 + c4]
                                 : make_float4(0.f, 0.f, 0.f, 0.f);
            sA[r][c4 + 0] = tf32r(v.x);
            sA[r][c4 + 1] = tf32r(v.y);
            sA[r][c4 + 2] = tf32r(v.z);
            sA[r][c4 + 3] = tf32r(v.w);
        }
#pragma unroll
        for (int it = 0; it < 2; it++) {
            int i = tid + it * 256;
            int r = i >> 5, c4 = (i & 31) * 4;
            float4 v = *(const float4*)&W[(size_t)(k0 + r) * NF + c4];
            sW[r][c4 + 0] = tf32r(v.x);
            sW[r][c4 + 1] = tf32r(v.y);
            sW[r][c4 + 2] = tf32r(v.z);
            sW[r][c4 + 3] = tf32r(v.w);
        }
        __syncthreads();

#pragma unroll
        for (int ks = 0; ks < 2; ks++) {
            int kb = ks * 8;
            uint32_t af[4][4];
#pragma unroll
            for (int mt = 0; mt < 4; mt++) {
                int ar = warp_m * 64 + mt * 16 + (lane >> 2);
                int ac = kb + (lane & 3);
                af[mt][0] = __float_as_uint(sA[ar][ac]);
                af[mt][1] = __float_as_uint(sA[ar + 8][ac]);
                af[mt][2] = __float_as_uint(sA[ar][ac + 4]);
                af[mt][3] = __float_as_uint(sA[ar + 8][ac + 4]);
            }
            uint32_t bf[4][2];
#pragma unroll
            for (int nt = 0; nt < 4; nt++) {
                int bn = warp_n * 32 + nt * 8 + (lane >> 2);
                int bk = kb + (lane & 3);
                bf[nt][0] = __float_as_uint(sW[bk][bn]);
                bf[nt][1] = __float_as_uint(sW[bk + 4][bn]);
            }
#pragma unroll
            for (int mt = 0; mt < 4; mt++)
#pragma unroll
                for (int nt = 0; nt < 4; nt++)
                    mma_tf32(acc[mt][nt], af[mt], bf[nt]);
        }
        __syncthreads();
    }

    // epilogue: *dinv, convert to fp16, store half2
#pragma unroll
    for (int mt = 0; mt < 4; mt++) {
        int r1 = row0 + warp_m * 64 + mt * 16 + (lane >> 2);
        int r2 = r1 + 8;
        float dv1 = (r1 < NN) ? g_dinv[r1] : 0.0f;
        float dv2 = (r2 < NN) ? g_dinv[r2] : 0.0f;
#pragma unroll
        for (int nt = 0; nt < 4; nt++) {
            int h2i = warp_n * 16 + nt * 4 + (lane & 3);   // half2 column index
            if (r1 < NN)
                g_H[(size_t)r1 * 64 + h2i] = __float22half2_rn(
                    make_float2(acc[mt][nt][0] * dv1, acc[mt][nt][1] * dv1));
            if (r2 < NN)
                g_H[(size_t)r2 * 64 + h2i] = __float22half2_rn(
                    make_float2(acc[mt][nt][2] * dv2, acc[mt][nt][3] * dv2));
        }
    }
}

// ---- shared gather core: 4-ahead index batching for MLP ----
__device__ __forceinline__ void gather_row(
    int node, int lane, float& ax, float& ay, float& az, float& aw)
{
    const __half2* hs = g_H;
    size_t lidx = (size_t)node * 64 + lane * 2;
    __half2 p0 = hs[lidx], p1 = hs[lidx + 1];
    float2 f0 = __half22float2(p0), f1 = __half22float2(p1);
    ax = f0.x; ay = f0.y; az = f1.x; aw = f1.y;   // self-loop term

    int s = g_start[node], c = g_cnt[node];
    int j = 0;
    for (; j + 4 <= c; j += 4) {
        int i0 = g_col[s + j + 0];
        int i1 = g_col[s + j + 1];
        int i2 = g_col[s + j + 2];
        int i3 = g_col[s + j + 3];
        __half2 a0 = hs[(size_t)i0 * 64 + lane * 2], b0 = hs[(size_t)i0 * 64 + lane * 2 + 1];
        __half2 a1 = hs[(size_t)i1 * 64 + lane * 2], b1 = hs[(size_t)i1 * 64 + lane * 2 + 1];
        __half2 a2 = hs[(size_t)i2 * 64 + lane * 2], b2 = hs[(size_t)i2 * 64 + lane * 2 + 1];
        __half2 a3 = hs[(size_t)i3 * 64 + lane * 2], b3 = hs[(size_t)i3 * 64 + lane * 2 + 1];
        float2 u0 = __half22float2(a0), v0 = __half22float2(b0);
        float2 u1 = __half22float2(a1), v1 = __half22float2(b1);
        float2 u2 = __half22float2(a2), v2 = __half22float2(b2);
        float2 u3 = __half22float2(a3), v3 = __half22float2(b3);
        ax += u0.x + u1.x + u2.x + u3.x;
        ay += u0.y + u1.y + u2.y + u3.y;
        az += v0.x + v1.x + v2.x + v3.x;
        aw += v0.y + v1.y + v2.y + v3.y;
    }
    for (; j < c; j++) {
        int src = g_col[s + j];
        size_t si = (size_t)src * 64 + lane * 2;
        __half2 q0 = hs[si], q1 = hs[si + 1];
        float2 g0 = __half22float2(q0), g1 = __half22float2(q1);
        ax += g0.x; ay += g0.y; az += g1.x; aw += g1.y;
    }
}

// ---- gather + relu: g_B0[n,:] = relu(dinv[n]*(hs[n]+sum_in hs[src]) + b) ----
__global__ __launch_bounds__(256) void k_gather_relu(const float* __restrict__ bias)
{
    int warp = (blockIdx.x * blockDim.x + threadIdx.x) >> 5;
    if (warp >= NN) return;
    int lane = threadIdx.x & 31;

    float ax, ay, az, aw;
    gather_row(warp, lane, ax, ay, az, aw);

    float dv = g_dinv[warp];
    float4 b4 = ((const float4*)bias)[lane];
    float4 o;
    o.x = fmaxf(ax * dv + b4.x, 0.0f);
    o.y = fmaxf(ay * dv + b4.y, 0.0f);
    o.z = fmaxf(az * dv + b4.z, 0.0f);
    o.w = fmaxf(aw * dv + b4.w, 0.0f);
    ((float4*)g_B0)[(size_t)warp * 32 + lane] = o;
}

// ---- layer-2 gather fused with relu + Wout dot + pooling sum (reads g_H) ----
__global__ __launch_bounds__(256) void k_gather_pool(
    const float* __restrict__ bias, const float* __restrict__ Wout,
    const int* __restrict__ batch)
{
    int warp = (blockIdx.x * blockDim.x + threadIdx.x) >> 5;
    if (warp >= NN) return;
    int lane = threadIdx.x & 31;

    float ax, ay, az, aw;
    gather_row(warp, lane, ax, ay, az, aw);

    float dv = g_dinv[warp];
    float4 b4 = ((const float4*)bias)[lane];
    float4 w4 = ((const float4*)Wout)[lane];
    float h0 = fmaxf(ax * dv + b4.x, 0.0f);
    float h1 = fmaxf(ay * dv + b4.y, 0.0f);
    float h2 = fmaxf(az * dv + b4.z, 0.0f);
    float h3 = fmaxf(aw * dv + b4.w, 0.0f);
    float sdot = h0 * w4.x + h1 * w4.y + h2 * w4.z + h3 * w4.w;
#pragma unroll
    for (int off = 16; off > 0; off >>= 1)
        sdot += __shfl_down_sync(0xffffffffu, sdot, off);
    if (lane == 0)
        atomicAdd(&g_pool[batch[warp]], sdot);
}

__global__ void k_final(float* __restrict__ out, const float* __restrict__ bout) {
    int g = blockIdx.x * blockDim.x + threadIdx.x;
    if (g >= NG) return;
    float c = fmaxf((float)g_gcnt[g], 1.0f);
    out[g] = g_pool[g] / c + bout[0];
}

// ---------------- launch (kernel launches only; graph-capturable) ----------------
extern "C" void kernel_launch(void* const* d_in, const int* in_sizes, int n_in,
                              void* d_out, int out_size)
{
    const float* x     = (const float*)d_in[0];
    const int*   ei    = (const int*)d_in[1];     // int32 (JAX x64 disabled)
    const int*   batch = (const int*)d_in[2];
    const float* W1    = (const float*)d_in[3];
    const float* b1    = (const float*)d_in[4];
    const float* W2    = (const float*)d_in[5];
    const float* b2    = (const float*)d_in[6];
    const float* Wout  = (const float*)d_in[7];
    const float* bout  = (const float*)d_in[8];
    float*       out   = (float*)d_out;

    const int TB = 256;
    // graph preprocessing (rebuilt every call; deterministic)
    k_init <<<(NN + TB - 1) / TB, TB>>>();
    k_deg  <<<(NE + TB - 1) / TB, TB>>>(ei, batch);
    k_scan1<<<SCAN_NB, SCAN_BS>>>();
    k_scan2<<<1, 128>>>();
    k_scan3<<<(NN + TB - 1) / TB, TB>>>();
    k_fill <<<(NE + TB - 1) / TB, TB>>>(ei);

    // layer 1: g_H = fp16((x@W1)*dinv)  ->  g_B0 = relu(dinv*(self + gather) + b1)
    k_mma_gemm<false><<<NT, 256>>>(x, W1);
    k_gather_relu<<<(NN * 32 + TB - 1) / TB, TB>>>(b1);

    // layer 2: g_H = fp16((g_B0@W2)*dinv) -> fused gather+relu+Wout-dot+pool
    k_mma_gemm<true><<<NT, 256>>>(nullptr, W2);
    k_gather_pool<<<(NN * 32 + TB - 1) / TB, TB>>>(b2, Wout, batch);

    k_final<<<(NG + TB - 1) / TB, TB>>>(out, bout);
}